// round 9
// baseline (speedup 1.0000x reference)
#include <cuda_runtime.h>
#include <cstdint>

// TinyRNN: B=4096, T=2048, I=1, H=12, O=2
// 4 lanes/group; lane k owns rows {3k..3k+2} of TWO batches (A,B) interleaved
// in one instruction stream to overlap the two serial chains.
// 8 groups/warp -> 16 batches/warp; 64-thread CTAs (32 batches); grid=128.
// Fully-packed 6-pair f32x2 tree per row (local column order), 9 shfl.xor per
// batch-step, tanh via MUFU.TANH.

#define T_TOTAL 2048
#define NCHUNK  32
#define CH      64
#define XSTRIDE 68   // 64 + 4 pad

__device__ __forceinline__ uint64_t pack2(float lo, float hi) {
    uint64_t r; asm("mov.b64 %0, {%1, %2};" : "=l"(r) : "f"(lo), "f"(hi)); return r;
}
__device__ __forceinline__ void unpack2(uint64_t v, float &lo, float &hi) {
    asm("mov.b64 {%0, %1}, %2;" : "=f"(lo), "=f"(hi) : "l"(v));
}
__device__ __forceinline__ uint64_t mul2(uint64_t a, uint64_t b) {
    uint64_t r; asm("mul.rn.f32x2 %0, %1, %2;" : "=l"(r) : "l"(a), "l"(b)); return r;
}
__device__ __forceinline__ uint64_t fma2(uint64_t a, uint64_t b, uint64_t c) {
    uint64_t r; asm("fma.rn.f32x2 %0, %1, %2, %3;" : "=l"(r) : "l"(a), "l"(b), "l"(c)); return r;
}
__device__ __forceinline__ uint64_t add2(uint64_t a, uint64_t b) {
    uint64_t r; asm("add.rn.f32x2 %0, %1, %2;" : "=l"(r) : "l"(a), "l"(b)); return r;
}
__device__ __forceinline__ float tanhf_hw(float x) {
    float r; asm("tanh.approx.f32 %0, %1;" : "=f"(r) : "f"(x)); return r;
}

__global__ void __launch_bounds__(64, 1) tinyrnn_kernel(
    const float* __restrict__ x,       // [4096, 2048, 1]
    const float* __restrict__ W_ih,    // [12, 1]
    const float* __restrict__ W_hh,    // [12, 12]
    const float* __restrict__ b_ih,    // [12]
    const float* __restrict__ b_hh,    // [12]
    const float* __restrict__ W_head,  // [2, 12]
    const float* __restrict__ b_head,  // [2]
    float* __restrict__ out)           // [4096, 2]
{
    __shared__ float sx[2][32 * XSTRIDE];

    const int tid  = threadIdx.x;            // 0..63
    const int lane = tid & 31;
    const int warp = tid >> 5;               // 0..1
    const int k    = lane & 3;               // lane within 4-lane group
    const int g    = lane >> 2;              // group within warp (0..7)
    const int bicA = warp * 16 + g;          // batch A in CTA (0..31)
    const int bicB = bicA + 8;               // batch B in CTA
    const int batchA = blockIdx.x * 32 + bicA;
    const int batchB = blockIdx.x * 32 + bicB;

    // local column order: c[3d+i] = 3*(k^d)+i
    int cidx[12];
#pragma unroll
    for (int d = 0; d < 4; d++) {
        const int p = k ^ d;
#pragma unroll
        for (int i = 0; i < 3; i++) cidx[3 * d + i] = 3 * p + i;
    }

    // weights per owned row r=3k+i, packed per local column pair (shared A/B)
    uint64_t Wc[3][6];
    float A[3], Bx[3];
#pragma unroll
    for (int i = 0; i < 3; i++) {
        const int r = 3 * k + i;
#pragma unroll
        for (int j = 0; j < 6; j++)
            Wc[i][j] = pack2(W_hh[r * 12 + cidx[2 * j]],
                             W_hh[r * 12 + cidx[2 * j + 1]]);
        A[i]  = b_ih[r] + b_hh[r];
        Bx[i] = W_ih[r];
    }

    const float* xcta = x + (size_t)blockIdx.x * 32 * T_TOTAL;

    // --- cp.async chunk prefetch: 32 batches x 64 steps = 512 float4 ---
    auto prefetch = [&](int c, int buf) {
#pragma unroll
        for (int rr = 0; rr < 8; rr++) {
            int flat = rr * 64 + tid;        // 0..511
            int b    = flat >> 4;
            int q    = flat & 15;
            const float* src = xcta + (size_t)b * T_TOTAL + c * CH + q * 4;
            unsigned dst = (unsigned)__cvta_generic_to_shared(
                &sx[buf][b * XSTRIDE + q * 4]);
            asm volatile("cp.async.ca.shared.global [%0], [%1], 16;\n"
                         :: "r"(dst), "l"(src));
        }
        asm volatile("cp.async.commit_group;\n");
    };

    prefetch(0, 0);

    float hA0 = 0.0f, hA1 = 0.0f, hA2 = 0.0f;
    float hB0 = 0.0f, hB1 = 0.0f, hB2 = 0.0f;

    for (int c = 0; c < NCHUNK; c++) {
        const int cur = c & 1;
        if (c + 1 < NCHUNK) {
            prefetch(c + 1, cur ^ 1);
            asm volatile("cp.async.wait_group 1;\n");
        } else {
            asm volatile("cp.async.wait_group 0;\n");
        }
        __syncthreads();

        const float* xsA = &sx[cur][bicA * XSTRIDE];
        const float* xsB = &sx[cur][bicB * XSTRIDE];

#pragma unroll 2
        for (int tt = 0; tt < CH; tt++) {
            const float xtA = xsA[tt];
            const float xtB = xsB[tt];

            // exchanges for both batches (independent; overlap in MIO)
            const float a0A = __shfl_xor_sync(0xffffffffu, hA0, 1, 4);
            const float a0B = __shfl_xor_sync(0xffffffffu, hB0, 1, 4);
            const float a1A = __shfl_xor_sync(0xffffffffu, hA1, 1, 4);
            const float a1B = __shfl_xor_sync(0xffffffffu, hB1, 1, 4);
            const float a2A = __shfl_xor_sync(0xffffffffu, hA2, 1, 4);
            const float a2B = __shfl_xor_sync(0xffffffffu, hB2, 1, 4);
            const float b0A = __shfl_xor_sync(0xffffffffu, hA0, 2, 4);
            const float b0B = __shfl_xor_sync(0xffffffffu, hB0, 2, 4);
            const float b1A = __shfl_xor_sync(0xffffffffu, hA1, 2, 4);
            const float b1B = __shfl_xor_sync(0xffffffffu, hB1, 2, 4);
            const float b2A = __shfl_xor_sync(0xffffffffu, hA2, 2, 4);
            const float b2B = __shfl_xor_sync(0xffffffffu, hB2, 2, 4);
            const float c0A = __shfl_xor_sync(0xffffffffu, hA0, 3, 4);
            const float c0B = __shfl_xor_sync(0xffffffffu, hB0, 3, 4);
            const float c1A = __shfl_xor_sync(0xffffffffu, hA1, 3, 4);
            const float c1B = __shfl_xor_sync(0xffffffffu, hB1, 3, 4);
            const float c2A = __shfl_xor_sync(0xffffffffu, hA2, 3, 4);
            const float c2B = __shfl_xor_sync(0xffffffffu, hB2, 3, 4);

            // u-terms (off chain)
            const float uA0 = fmaf(xtA, Bx[0], A[0]);
            const float uA1 = fmaf(xtA, Bx[1], A[1]);
            const float uA2 = fmaf(xtA, Bx[2], A[2]);
            const float uB0 = fmaf(xtB, Bx[0], A[0]);
            const float uB1 = fmaf(xtB, Bx[1], A[1]);
            const float uB2 = fmaf(xtB, Bx[2], A[2]);

            // column pairs (local order)
            const uint64_t PA0 = pack2(hA0, hA1);
            const uint64_t PA1 = pack2(hA2, a0A);
            const uint64_t PA2 = pack2(a1A, a2A);
            const uint64_t PA3 = pack2(b0A, b1A);
            const uint64_t PA4 = pack2(b2A, c0A);
            const uint64_t PA5 = pack2(c1A, c2A);
            const uint64_t PB0 = pack2(hB0, hB1);
            const uint64_t PB1 = pack2(hB2, a0B);
            const uint64_t PB2 = pack2(a1B, a2B);
            const uint64_t PB3 = pack2(b0B, b1B);
            const uint64_t PB4 = pack2(b2B, c0B);
            const uint64_t PB5 = pack2(c1B, c2B);

            const float uuA[3] = {uA0, uA1, uA2};
            const float uuB[3] = {uB0, uB1, uB2};
            float hnA[3], hnB[3];
#pragma unroll
            for (int i = 0; i < 3; i++) {
                uint64_t aA = fma2(Wc[i][0], PA0, pack2(uuA[i], 0.0f));
                uint64_t bA = mul2(Wc[i][1], PA1);
                uint64_t aB = fma2(Wc[i][0], PB0, pack2(uuB[i], 0.0f));
                uint64_t bB = mul2(Wc[i][1], PB1);
                aA = fma2(Wc[i][2], PA2, aA);
                bA = fma2(Wc[i][3], PA3, bA);
                aB = fma2(Wc[i][2], PB2, aB);
                bB = fma2(Wc[i][3], PB3, bB);
                aA = fma2(Wc[i][4], PA4, aA);
                bA = fma2(Wc[i][5], PA5, bA);
                aB = fma2(Wc[i][4], PB4, aB);
                bB = fma2(Wc[i][5], PB5, bB);
                float loA, hiA, loB, hiB;
                unpack2(add2(aA, bA), loA, hiA);
                unpack2(add2(aB, bB), loB, hiB);
                hnA[i] = tanhf_hw(loA + hiA);
                hnB[i] = tanhf_hw(loB + hiB);
            }
            hA0 = hnA[0]; hA1 = hnA[1]; hA2 = hnA[2];
            hB0 = hnB[0]; hB1 = hnB[1]; hB2 = hnB[2];
        }
        __syncthreads();
    }

    // --- head: rebuild full h per batch; for k==0 local order == global ---
    float gA[12], gB[12];
    gA[0] = hA0; gA[1] = hA1; gA[2] = hA2;
    gB[0] = hB0; gB[1] = hB1; gB[2] = hB2;
#pragma unroll
    for (int d = 1; d < 4; d++) {
        gA[3 * d + 0] = __shfl_xor_sync(0xffffffffu, hA0, d, 4);
        gA[3 * d + 1] = __shfl_xor_sync(0xffffffffu, hA1, d, 4);
        gA[3 * d + 2] = __shfl_xor_sync(0xffffffffu, hA2, d, 4);
        gB[3 * d + 0] = __shfl_xor_sync(0xffffffffu, hB0, d, 4);
        gB[3 * d + 1] = __shfl_xor_sync(0xffffffffu, hB1, d, 4);
        gB[3 * d + 2] = __shfl_xor_sync(0xffffffffu, hB2, d, 4);
    }

    if (k == 0) {
        float o0A = b_head[0], o1A = b_head[1];
        float o0B = b_head[0], o1B = b_head[1];
#pragma unroll
        for (int m = 0; m < 12; m++) {
            o0A = fmaf(W_head[m],      gA[m], o0A);
            o1A = fmaf(W_head[12 + m], gA[m], o1A);
            o0B = fmaf(W_head[m],      gB[m], o0B);
            o1B = fmaf(W_head[12 + m], gB[m], o1B);
        }
        out[batchA * 2 + 0] = o0A;
        out[batchA * 2 + 1] = o1A;
        out[batchB * 2 + 0] = o0B;
        out[batchB * 2 + 1] = o1B;
    }
}

extern "C" void kernel_launch(void* const* d_in, const int* in_sizes, int n_in,
                              void* d_out, int out_size)
{
    const float* x      = (const float*)d_in[0];
    const float* W_ih   = (const float*)d_in[1];
    const float* W_hh   = (const float*)d_in[2];
    const float* b_ih   = (const float*)d_in[3];
    const float* b_hh   = (const float*)d_in[4];
    const float* W_head = (const float*)d_in[5];
    const float* b_head = (const float*)d_in[6];
    float* out = (float*)d_out;

    tinyrnn_kernel<<<128, 64>>>(x, W_ih, W_hh, b_ih, b_hh, W_head, b_head, out);
}

// round 10
// speedup vs baseline: 1.3678x; 1.3678x over previous
#include <cuda_runtime.h>
#include <cuda_fp16.h>
#include <cstdint>

// TinyRNN: B=4096, T=2048, I=1, H=12, O=2
// 4 lanes/batch; lane k owns rows {3k..3k+2}; 8 batches/warp;
// 128-thread CTAs (32 batches), grid=128 -> 512 warps (1/SMSP on 128 SMs).
// Exchange: (h0,h1) as ONE half2 word + h2 as f32 -> 6 shfl.xor per step
// (down from 9; SHFL rt~8 is the binding pipe). tanh via MUFU.TANH.
// Tree: 4 packed (h0,h1)-column f32x2 pairs; 4 late h2-columns via flat
// scalar FFMA tail ordered by shfl arrival (c2 last).

#define T_TOTAL 2048
#define NCHUNK  32
#define CH      64
#define XSTRIDE 68   // 64 + 4 pad

__device__ __forceinline__ uint64_t pack2(float lo, float hi) {
    uint64_t r; asm("mov.b64 %0, {%1, %2};" : "=l"(r) : "f"(lo), "f"(hi)); return r;
}
__device__ __forceinline__ void unpack2(uint64_t v, float &lo, float &hi) {
    asm("mov.b64 {%0, %1}, %2;" : "=f"(lo), "=f"(hi) : "l"(v));
}
__device__ __forceinline__ uint64_t mul2(uint64_t a, uint64_t b) {
    uint64_t r; asm("mul.rn.f32x2 %0, %1, %2;" : "=l"(r) : "l"(a), "l"(b)); return r;
}
__device__ __forceinline__ uint64_t fma2(uint64_t a, uint64_t b, uint64_t c) {
    uint64_t r; asm("fma.rn.f32x2 %0, %1, %2, %3;" : "=l"(r) : "l"(a), "l"(b), "l"(c)); return r;
}
__device__ __forceinline__ uint64_t add2(uint64_t a, uint64_t b) {
    uint64_t r; asm("add.rn.f32x2 %0, %1, %2;" : "=l"(r) : "l"(a), "l"(b)); return r;
}
__device__ __forceinline__ float tanhf_hw(float x) {
    float r; asm("tanh.approx.f32 %0, %1;" : "=f"(r) : "f"(x)); return r;
}
// pack two f32 -> f16x2 word (lo = a, hi = b)
__device__ __forceinline__ unsigned pack_f16x2(float a, float b) {
    unsigned u;
    asm("cvt.rn.f16x2.f32 %0, %2, %1;" : "=r"(u) : "f"(a), "f"(b));
    return u;
}
// unpack f16x2 word -> packed f32x2 (lo, hi)
__device__ __forceinline__ uint64_t f16x2_to_f32x2(unsigned u) {
    float lo, hi;
    asm("{ .reg .b16 l, h;\n\t"
        "  mov.b32 {l, h}, %2;\n\t"
        "  cvt.f32.f16 %0, l;\n\t"
        "  cvt.f32.f16 %1, h; }"
        : "=f"(lo), "=f"(hi) : "r"(u));
    return pack2(lo, hi);
}

__global__ void __launch_bounds__(128, 1) tinyrnn_kernel(
    const float* __restrict__ x,       // [4096, 2048, 1]
    const float* __restrict__ W_ih,    // [12, 1]
    const float* __restrict__ W_hh,    // [12, 12]
    const float* __restrict__ b_ih,    // [12]
    const float* __restrict__ b_hh,    // [12]
    const float* __restrict__ W_head,  // [2, 12]
    const float* __restrict__ b_head,  // [2]
    float* __restrict__ out)           // [4096, 2]
{
    __shared__ float sx[2][32 * XSTRIDE];

    const int tid  = threadIdx.x;
    const int lane = tid & 31;
    const int warp = tid >> 5;
    const int k    = lane & 3;              // lane within 4-lane group
    const int wb   = lane >> 2;             // batch within warp (0..7)
    const int bic  = warp * 8 + wb;         // batch in CTA (0..31)
    const int batch = blockIdx.x * 32 + bic;

    // weights per owned row r=3k+i:
    //  Wp[i][d]: packed f32x2 for columns (3(k^d), 3(k^d)+1)
    //  ws[i][d]: scalar for column 3(k^d)+2
    uint64_t Wp[3][4];
    float    ws[3][4];
    float A[3], Bx[3];
#pragma unroll
    for (int i = 0; i < 3; i++) {
        const int r = 3 * k + i;
#pragma unroll
        for (int d = 0; d < 4; d++) {
            const int cb = 3 * (k ^ d);
            Wp[i][d] = pack2(W_hh[r * 12 + cb], W_hh[r * 12 + cb + 1]);
            ws[i][d] = W_hh[r * 12 + cb + 2];
        }
        A[i]  = b_ih[r] + b_hh[r];
        Bx[i] = W_ih[r];
    }

    const float* xcta = x + (size_t)blockIdx.x * 32 * T_TOTAL;

    // --- cp.async chunk prefetch: 32 batches x 64 steps = 512 float4 ---
    auto prefetch = [&](int c, int buf) {
#pragma unroll
        for (int rr = 0; rr < 4; rr++) {
            int flat = rr * 128 + tid;      // 0..511
            int b    = flat >> 4;
            int q    = flat & 15;
            const float* src = xcta + (size_t)b * T_TOTAL + c * CH + q * 4;
            unsigned dst = (unsigned)__cvta_generic_to_shared(
                &sx[buf][b * XSTRIDE + q * 4]);
            asm volatile("cp.async.ca.shared.global [%0], [%1], 16;\n"
                         :: "r"(dst), "l"(src));
        }
        asm volatile("cp.async.commit_group;\n");
    };

    prefetch(0, 0);

    float h0 = 0.0f, h1 = 0.0f, h2 = 0.0f;  // own rows 3k..3k+2

    for (int c = 0; c < NCHUNK; c++) {
        const int cur = c & 1;
        if (c + 1 < NCHUNK) {
            prefetch(c + 1, cur ^ 1);
            asm volatile("cp.async.wait_group 1;\n");
        } else {
            asm volatile("cp.async.wait_group 0;\n");
        }
        __syncthreads();

        const float* xs = &sx[cur][bic * XSTRIDE];

#pragma unroll 2
        for (int tt = 0; tt < CH; tt++) {
            const float xt = xs[tt];
            // bias/x init terms, off the serial chain
            const uint64_t U0 = pack2(fmaf(xt, Bx[0], A[0]), 0.0f);
            const uint64_t U1 = pack2(fmaf(xt, Bx[1], A[1]), 0.0f);
            const uint64_t U2 = pack2(fmaf(xt, Bx[2], A[2]), 0.0f);

            // pack own (h0,h1) once; exchange: 3 half2 shfls + 3 f32 h2 shfls
            const unsigned own01 = pack_f16x2(h0, h1);
            const unsigned a01 = __shfl_xor_sync(0xffffffffu, own01, 1, 4);
            const unsigned b01 = __shfl_xor_sync(0xffffffffu, own01, 2, 4);
            const unsigned c01 = __shfl_xor_sync(0xffffffffu, own01, 3, 4);
            const float    a2  = __shfl_xor_sync(0xffffffffu, h2, 1, 4);
            const float    b2  = __shfl_xor_sync(0xffffffffu, h2, 2, 4);
            const float    c2  = __shfl_xor_sync(0xffffffffu, h2, 3, 4);

            // packed (h0,h1) pairs per direction (own stays f32)
            const uint64_t P0 = pack2(h0, h1);
            const uint64_t P1 = f16x2_to_f32x2(a01);
            const uint64_t P2 = f16x2_to_f32x2(b01);
            const uint64_t P3 = f16x2_to_f32x2(c01);

            float hn[3];
            const uint64_t UU[3] = {U0, U1, U2};
#pragma unroll
            for (int i = 0; i < 3; i++) {
                uint64_t aA = fma2(Wp[i][0], P0, UU[i]);
                uint64_t aB = mul2(Wp[i][1], P1);
                aA = fma2(Wp[i][2], P2, aA);
                aB = fma2(Wp[i][3], P3, aB);
                float lo, hi;
                unpack2(add2(aA, aB), lo, hi);
                float s = lo + hi;
                // flat scalar tail, ordered by arrival: own h2, a2, b2, c2
                s = fmaf(ws[i][0], h2, s);
                s = fmaf(ws[i][1], a2, s);
                s = fmaf(ws[i][2], b2, s);
                s = fmaf(ws[i][3], c2, s);
                hn[i] = tanhf_hw(s);
            }
            h0 = hn[0]; h1 = hn[1]; h2 = hn[2];
        }
        __syncthreads();
    }

    // --- head: rebuild full h (f32 shfls; negligible cost) ---
    float g[12];
    g[0] = h0; g[1] = h1; g[2] = h2;
#pragma unroll
    for (int d = 1; d < 4; d++) {
        g[3 * d + 0] = __shfl_xor_sync(0xffffffffu, h0, d, 4);
        g[3 * d + 1] = __shfl_xor_sync(0xffffffffu, h1, d, 4);
        g[3 * d + 2] = __shfl_xor_sync(0xffffffffu, h2, d, 4);
    }

    if (k == 0) {
        float o0 = b_head[0];
        float o1 = b_head[1];
#pragma unroll
        for (int m = 0; m < 12; m++) {
            o0 = fmaf(W_head[m],      g[m], o0);
            o1 = fmaf(W_head[12 + m], g[m], o1);
        }
        out[batch * 2 + 0] = o0;
        out[batch * 2 + 1] = o1;
    }
}

extern "C" void kernel_launch(void* const* d_in, const int* in_sizes, int n_in,
                              void* d_out, int out_size)
{
    const float* x      = (const float*)d_in[0];
    const float* W_ih   = (const float*)d_in[1];
    const float* W_hh   = (const float*)d_in[2];
    const float* b_ih   = (const float*)d_in[3];
    const float* b_hh   = (const float*)d_in[4];
    const float* W_head = (const float*)d_in[5];
    const float* b_head = (const float*)d_in[6];
    float* out = (float*)d_out;

    tinyrnn_kernel<<<128, 128>>>(x, W_ih, W_hh, b_ih, b_hh, W_head, b_head, out);
}

// round 11
// speedup vs baseline: 1.4555x; 1.0642x over previous
#include <cuda_runtime.h>
#include <cstdint>

// TinyRNN: B=4096, T=2048, I=1, H=12, O=2
// 4 lanes/batch; lane k owns rows {3k..3k+2}; 8 batches/warp;
// 128-thread CTAs (32 batches), grid=128 -> 512 warps (1/SMSP on 128 SMs).
// Exchange via same-warp shared memory, NO syncwarp (same-warp MIO in-order):
//   3x STS.32 (own h) -> 3x LDS.128 (all 12 h, pre-paired for f32x2).
// Tree: 6 packed column-pair fma2 per row, hadd, tanh via MUFU.TANH.

#define T_TOTAL 2048
#define NCHUNK  32
#define CH      64
#define XSTRIDE 68   // 64 + 4 pad
#define EXSTRIDE 20  // floats per group exchange slot (80B, conflict-free)

__device__ __forceinline__ uint64_t pack2(float lo, float hi) {
    uint64_t r; asm("mov.b64 %0, {%1, %2};" : "=l"(r) : "f"(lo), "f"(hi)); return r;
}
__device__ __forceinline__ uint64_t pack2u(uint32_t lo, uint32_t hi) {
    uint64_t r; asm("mov.b64 %0, {%1, %2};" : "=l"(r) : "r"(lo), "r"(hi)); return r;
}
__device__ __forceinline__ void unpack2(uint64_t v, float &lo, float &hi) {
    asm("mov.b64 {%0, %1}, %2;" : "=f"(lo), "=f"(hi) : "l"(v));
}
__device__ __forceinline__ uint64_t mul2(uint64_t a, uint64_t b) {
    uint64_t r; asm("mul.rn.f32x2 %0, %1, %2;" : "=l"(r) : "l"(a), "l"(b)); return r;
}
__device__ __forceinline__ uint64_t fma2(uint64_t a, uint64_t b, uint64_t c) {
    uint64_t r; asm("fma.rn.f32x2 %0, %1, %2, %3;" : "=l"(r) : "l"(a), "l"(b), "l"(c)); return r;
}
__device__ __forceinline__ uint64_t add2(uint64_t a, uint64_t b) {
    uint64_t r; asm("add.rn.f32x2 %0, %1, %2;" : "=l"(r) : "l"(a), "l"(b)); return r;
}
__device__ __forceinline__ float tanhf_hw(float x) {
    float r; asm("tanh.approx.f32 %0, %1;" : "=f"(r) : "f"(x)); return r;
}

__global__ void __launch_bounds__(128, 1) tinyrnn_kernel(
    const float* __restrict__ x,       // [4096, 2048, 1]
    const float* __restrict__ W_ih,    // [12, 1]
    const float* __restrict__ W_hh,    // [12, 12]
    const float* __restrict__ b_ih,    // [12]
    const float* __restrict__ b_hh,    // [12]
    const float* __restrict__ W_head,  // [2, 12]
    const float* __restrict__ b_head,  // [2]
    float* __restrict__ out)           // [4096, 2]
{
    __shared__ float sx[2][32 * XSTRIDE];
    __shared__ __align__(16) float sex[32 * EXSTRIDE];

    const int tid  = threadIdx.x;
    const int lane = tid & 31;
    const int warp = tid >> 5;
    const int k    = lane & 3;              // lane within 4-lane group
    const int wb   = lane >> 2;             // group within warp (0..7)
    const int bic  = warp * 8 + wb;         // batch in CTA (0..31)
    const int batch = blockIdx.x * 32 + bic;

    // weights per owned row r=3k+i, packed per GLOBAL column pair (2j, 2j+1)
    uint64_t Wc[3][6];
    float A[3], Bx[3];
#pragma unroll
    for (int i = 0; i < 3; i++) {
        const int r = 3 * k + i;
#pragma unroll
        for (int j = 0; j < 6; j++)
            Wc[i][j] = pack2(W_hh[r * 12 + 2 * j], W_hh[r * 12 + 2 * j + 1]);
        A[i]  = b_ih[r] + b_hh[r];
        Bx[i] = W_ih[r];
    }

    // exchange slot addresses (group slot = bic*20 floats; lane writes m=3k..3k+2)
    const unsigned exb = (unsigned)__cvta_generic_to_shared(&sex[bic * EXSTRIDE]);
    const unsigned st0 = exb + 12u * (unsigned)k;   // m = 3k
    const unsigned st1 = st0 + 4u;                  // m = 3k+1
    const unsigned st2 = st0 + 8u;                  // m = 3k+2

    const float* xcta = x + (size_t)blockIdx.x * 32 * T_TOTAL;

    // --- cp.async chunk prefetch: 32 batches x 64 steps = 512 float4 ---
    auto prefetch = [&](int c, int buf) {
#pragma unroll
        for (int rr = 0; rr < 4; rr++) {
            int flat = rr * 128 + tid;      // 0..511
            int b    = flat >> 4;
            int q    = flat & 15;
            const float* src = xcta + (size_t)b * T_TOTAL + c * CH + q * 4;
            unsigned dst = (unsigned)__cvta_generic_to_shared(
                &sx[buf][b * XSTRIDE + q * 4]);
            asm volatile("cp.async.ca.shared.global [%0], [%1], 16;\n"
                         :: "r"(dst), "l"(src));
        }
        asm volatile("cp.async.commit_group;\n");
    };

    prefetch(0, 0);

    float h0 = 0.0f, h1 = 0.0f, h2 = 0.0f;  // own rows 3k..3k+2

    for (int c = 0; c < NCHUNK; c++) {
        const int cur = c & 1;
        if (c + 1 < NCHUNK) {
            prefetch(c + 1, cur ^ 1);
            asm volatile("cp.async.wait_group 1;\n");
        } else {
            asm volatile("cp.async.wait_group 0;\n");
        }
        __syncthreads();

        const float* xs = &sx[cur][bic * XSTRIDE];

#pragma unroll 4
        for (int tt = 0; tt < CH; tt++) {
            const float xt = xs[tt];
            // bias/x init terms, off the serial chain
            const uint64_t U0 = pack2(fmaf(xt, Bx[0], A[0]), 0.0f);
            const uint64_t U1 = pack2(fmaf(xt, Bx[1], A[1]), 0.0f);
            const uint64_t U2 = pack2(fmaf(xt, Bx[2], A[2]), 0.0f);

            // publish own h (program order; same-warp MIO processes in order)
            asm volatile("st.shared.f32 [%0], %1;" :: "r"(st0), "f"(h0));
            asm volatile("st.shared.f32 [%0], %1;" :: "r"(st1), "f"(h1));
            asm volatile("st.shared.f32 [%0], %1;" :: "r"(st2), "f"(h2));
            // read all 12 h as three aligned quads (after STS in MIO order)
            uint32_t q0, q1, q2, q3, q4, q5, q6, q7, q8, q9, qa, qb;
            asm volatile("ld.shared.v4.b32 {%0,%1,%2,%3}, [%4];"
                         : "=r"(q0), "=r"(q1), "=r"(q2), "=r"(q3) : "r"(exb));
            asm volatile("ld.shared.v4.b32 {%0,%1,%2,%3}, [%4];"
                         : "=r"(q4), "=r"(q5), "=r"(q6), "=r"(q7) : "r"(exb + 16u));
            asm volatile("ld.shared.v4.b32 {%0,%1,%2,%3}, [%4];"
                         : "=r"(q8), "=r"(q9), "=r"(qa), "=r"(qb) : "r"(exb + 32u));

            const uint64_t P0 = pack2u(q0, q1), P1 = pack2u(q2, q3);
            const uint64_t P2 = pack2u(q4, q5), P3 = pack2u(q6, q7);
            const uint64_t P4 = pack2u(q8, q9), P5 = pack2u(qa, qb);

            float hn[3];
            const uint64_t UU[3] = {U0, U1, U2};
#pragma unroll
            for (int i = 0; i < 3; i++) {
                uint64_t aA = fma2(Wc[i][0], P0, UU[i]);
                uint64_t aB = mul2(Wc[i][1], P1);
                aA = fma2(Wc[i][2], P2, aA);
                aB = fma2(Wc[i][3], P3, aB);
                aA = fma2(Wc[i][4], P4, aA);
                aB = fma2(Wc[i][5], P5, aB);
                float lo, hi;
                unpack2(add2(aA, aB), lo, hi);
                hn[i] = tanhf_hw(lo + hi);
            }
            h0 = hn[0]; h1 = hn[1]; h2 = hn[2];
        }
        __syncthreads();
    }

    // --- head: rebuild full h via shfl (one-time; negligible) ---
    float g[12];
    g[3 * k + 0] = h0; g[3 * k + 1] = h1; g[3 * k + 2] = h2;
#pragma unroll
    for (int d = 1; d < 4; d++) {
        const int p = k ^ d;
        g[3 * p + 0] = __shfl_xor_sync(0xffffffffu, h0, d, 4);
        g[3 * p + 1] = __shfl_xor_sync(0xffffffffu, h1, d, 4);
        g[3 * p + 2] = __shfl_xor_sync(0xffffffffu, h2, d, 4);
    }

    if (k == 0) {
        float o0 = b_head[0];
        float o1 = b_head[1];
#pragma unroll
        for (int m = 0; m < 12; m++) {
            o0 = fmaf(W_head[m],      g[m], o0);
            o1 = fmaf(W_head[12 + m], g[m], o1);
        }
        out[batch * 2 + 0] = o0;
        out[batch * 2 + 1] = o1;
    }
}

extern "C" void kernel_launch(void* const* d_in, const int* in_sizes, int n_in,
                              void* d_out, int out_size)
{
    const float* x      = (const float*)d_in[0];
    const float* W_ih   = (const float*)d_in[1];
    const float* W_hh   = (const float*)d_in[2];
    const float* b_ih   = (const float*)d_in[3];
    const float* b_hh   = (const float*)d_in[4];
    const float* W_head = (const float*)d_in[5];
    const float* b_head = (const float*)d_in[6];
    float* out = (float*)d_out;

    tinyrnn_kernel<<<128, 128>>>(x, W_ih, W_hh, b_ih, b_hh, W_head, b_head, out);
}

// round 12
// speedup vs baseline: 1.6099x; 1.1060x over previous
#include <cuda_runtime.h>
#include <cstdint>

// TinyRNN: B=4096, T=2048, I=1, H=12, O=2
// 4 lanes/batch; lane k owns rows {3k..3k+2}; 8 batches/warp;
// 128-thread CTAs (32 batches), grid=128 -> 512 warps (1/SMSP on 128 SMs).
// Exchange via same-warp shared memory, NO syncwarp (validated R11), with
// LANE-MAJOR layout: slot float m' = 4*i + k  (quad i = h_i of lanes 0..3).
//  -> LDS of quad 0 depends only on h0 (earliest tanh): pipeline starts early.
//  -> quad i gives two f32x2 column pairs: cols (i, 3+i) and (6+i, 9+i).
// Two fma2 chains, one pair per quad each; post-last-land = 2 fma2 + add2 +
// hadd + tanh. tanh via MUFU.TANH.

#define T_TOTAL 2048
#define NCHUNK  32
#define CH      64
#define XSTRIDE 68   // 64 + 4 pad
#define EXSTRIDE 20  // floats per group slot (80B: 16B-aligned, conflict-free)

__device__ __forceinline__ uint64_t pack2(float lo, float hi) {
    uint64_t r; asm("mov.b64 %0, {%1, %2};" : "=l"(r) : "f"(lo), "f"(hi)); return r;
}
__device__ __forceinline__ uint64_t pack2u(uint32_t lo, uint32_t hi) {
    uint64_t r; asm("mov.b64 %0, {%1, %2};" : "=l"(r) : "r"(lo), "r"(hi)); return r;
}
__device__ __forceinline__ void unpack2(uint64_t v, float &lo, float &hi) {
    asm("mov.b64 {%0, %1}, %2;" : "=f"(lo), "=f"(hi) : "l"(v));
}
__device__ __forceinline__ uint64_t mul2(uint64_t a, uint64_t b) {
    uint64_t r; asm("mul.rn.f32x2 %0, %1, %2;" : "=l"(r) : "l"(a), "l"(b)); return r;
}
__device__ __forceinline__ uint64_t fma2(uint64_t a, uint64_t b, uint64_t c) {
    uint64_t r; asm("fma.rn.f32x2 %0, %1, %2, %3;" : "=l"(r) : "l"(a), "l"(b), "l"(c)); return r;
}
__device__ __forceinline__ uint64_t add2(uint64_t a, uint64_t b) {
    uint64_t r; asm("add.rn.f32x2 %0, %1, %2;" : "=l"(r) : "l"(a), "l"(b)); return r;
}
__device__ __forceinline__ float tanhf_hw(float x) {
    float r; asm("tanh.approx.f32 %0, %1;" : "=f"(r) : "f"(x)); return r;
}

__global__ void __launch_bounds__(128, 1) tinyrnn_kernel(
    const float* __restrict__ x,       // [4096, 2048, 1]
    const float* __restrict__ W_ih,    // [12, 1]
    const float* __restrict__ W_hh,    // [12, 12]
    const float* __restrict__ b_ih,    // [12]
    const float* __restrict__ b_hh,    // [12]
    const float* __restrict__ W_head,  // [2, 12]
    const float* __restrict__ b_head,  // [2]
    float* __restrict__ out)           // [4096, 2]
{
    __shared__ float sx[2][32 * XSTRIDE];
    __shared__ __align__(16) float sex[32 * EXSTRIDE];

    const int tid  = threadIdx.x;
    const int lane = tid & 31;
    const int warp = tid >> 5;
    const int k    = lane & 3;              // lane within 4-lane group
    const int wb   = lane >> 2;             // group within warp (0..7)
    const int bic  = warp * 8 + wb;         // batch in CTA (0..31)
    const int batch = blockIdx.x * 32 + bic;

    // weights per owned row r=3k+i, regrouped for lane-major quads:
    // quad q, pair p -> global cols (3*(2p)+q, 3*(2p+1)+q)
    // chain A consumes pair p=0 of each quad; chain B pair p=1.
    uint64_t WA[3][3], WB[3][3];
    float A[3], Bx[3];
#pragma unroll
    for (int i = 0; i < 3; i++) {
        const int r = 3 * k + i;
#pragma unroll
        for (int q = 0; q < 3; q++) {
            WA[i][q] = pack2(W_hh[r * 12 + q],     W_hh[r * 12 + 3 + q]);
            WB[i][q] = pack2(W_hh[r * 12 + 6 + q], W_hh[r * 12 + 9 + q]);
        }
        A[i]  = b_ih[r] + b_hh[r];
        Bx[i] = W_ih[r];
    }

    // exchange slot addresses: float m' = 4*i + k  (lane-major)
    const unsigned exb = (unsigned)__cvta_generic_to_shared(&sex[bic * EXSTRIDE]);
    const unsigned st0 = exb + 4u * (unsigned)k;        // h0 -> quad 0
    const unsigned st1 = st0 + 16u;                     // h1 -> quad 1
    const unsigned st2 = st0 + 32u;                     // h2 -> quad 2

    const float* xcta = x + (size_t)blockIdx.x * 32 * T_TOTAL;

    // --- cp.async chunk prefetch: 32 batches x 64 steps = 512 float4 ---
    auto prefetch = [&](int c, int buf) {
#pragma unroll
        for (int rr = 0; rr < 4; rr++) {
            int flat = rr * 128 + tid;      // 0..511
            int b    = flat >> 4;
            int q    = flat & 15;
            const float* src = xcta + (size_t)b * T_TOTAL + c * CH + q * 4;
            unsigned dst = (unsigned)__cvta_generic_to_shared(
                &sx[buf][b * XSTRIDE + q * 4]);
            asm volatile("cp.async.ca.shared.global [%0], [%1], 16;\n"
                         :: "r"(dst), "l"(src));
        }
        asm volatile("cp.async.commit_group;\n");
    };

    prefetch(0, 0);

    float h0 = 0.0f, h1 = 0.0f, h2 = 0.0f;  // own rows 3k..3k+2

    for (int c = 0; c < NCHUNK; c++) {
        const int cur = c & 1;
        if (c + 1 < NCHUNK) {
            prefetch(c + 1, cur ^ 1);
            asm volatile("cp.async.wait_group 1;\n");
        } else {
            asm volatile("cp.async.wait_group 0;\n");
        }
        __syncthreads();

        const float* xs = &sx[cur][bic * XSTRIDE];

#pragma unroll 4
        for (int tt = 0; tt < CH; tt++) {
            const float xt = xs[tt];
            // bias/x init terms, off the serial chain
            const uint64_t U0 = pack2(fmaf(xt, Bx[0], A[0]), 0.0f);
            const uint64_t U1 = pack2(fmaf(xt, Bx[1], A[1]), 0.0f);
            const uint64_t U2 = pack2(fmaf(xt, Bx[2], A[2]), 0.0f);

            // interleaved STS/LDS: quad i depends ONLY on h_i (same-warp MIO
            // order guarantees each LDS sees the STS issued before it).
            uint32_t q0, q1, q2, q3, q4, q5, q6, q7, q8, q9, qa, qb;
            asm volatile("st.shared.f32 [%0], %1;" :: "r"(st0), "f"(h0));
            asm volatile("ld.shared.v4.b32 {%0,%1,%2,%3}, [%4];"
                         : "=r"(q0), "=r"(q1), "=r"(q2), "=r"(q3) : "r"(exb));
            asm volatile("st.shared.f32 [%0], %1;" :: "r"(st1), "f"(h1));
            asm volatile("ld.shared.v4.b32 {%0,%1,%2,%3}, [%4];"
                         : "=r"(q4), "=r"(q5), "=r"(q6), "=r"(q7) : "r"(exb + 16u));
            asm volatile("st.shared.f32 [%0], %1;" :: "r"(st2), "f"(h2));
            asm volatile("ld.shared.v4.b32 {%0,%1,%2,%3}, [%4];"
                         : "=r"(q8), "=r"(q9), "=r"(qa), "=r"(qb) : "r"(exb + 32u));

            // quad i -> pairs: (h over lanes 0,1) and (lanes 2,3)
            const uint64_t P0A = pack2u(q0, q1), P0B = pack2u(q2, q3);
            const uint64_t P1A = pack2u(q4, q5), P1B = pack2u(q6, q7);
            const uint64_t P2A = pack2u(q8, q9), P2B = pack2u(qa, qb);

            float hn[3];
            const uint64_t UU[3] = {U0, U1, U2};
#pragma unroll
            for (int i = 0; i < 3; i++) {
                // chain A: quad pairs p=0; chain B: p=1 — one pair per quad
                uint64_t aA = fma2(WA[i][0], P0A, UU[i]);
                uint64_t aB = mul2(WB[i][0], P0B);
                aA = fma2(WA[i][1], P1A, aA);
                aB = fma2(WB[i][1], P1B, aB);
                aA = fma2(WA[i][2], P2A, aA);
                aB = fma2(WB[i][2], P2B, aB);
                float lo, hi;
                unpack2(add2(aA, aB), lo, hi);
                hn[i] = tanhf_hw(lo + hi);
            }
            h0 = hn[0]; h1 = hn[1]; h2 = hn[2];
        }
        __syncthreads();
    }

    // --- head: rebuild full h via shfl (one-time; negligible) ---
    float g[12];
    g[3 * k + 0] = h0; g[3 * k + 1] = h1; g[3 * k + 2] = h2;
#pragma unroll
    for (int d = 1; d < 4; d++) {
        const int p = k ^ d;
        g[3 * p + 0] = __shfl_xor_sync(0xffffffffu, h0, d, 4);
        g[3 * p + 1] = __shfl_xor_sync(0xffffffffu, h1, d, 4);
        g[3 * p + 2] = __shfl_xor_sync(0xffffffffu, h2, d, 4);
    }

    if (k == 0) {
        float o0 = b_head[0];
        float o1 = b_head[1];
#pragma unroll
        for (int m = 0; m < 12; m++) {
            o0 = fmaf(W_head[m],      g[m], o0);
            o1 = fmaf(W_head[12 + m], g[m], o1);
        }
        out[batch * 2 + 0] = o0;
        out[batch * 2 + 1] = o1;
    }
}

extern "C" void kernel_launch(void* const* d_in, const int* in_sizes, int n_in,
                              void* d_out, int out_size)
{
    const float* x      = (const float*)d_in[0];
    const float* W_ih   = (const float*)d_in[1];
    const float* W_hh   = (const float*)d_in[2];
    const float* b_ih   = (const float*)d_in[3];
    const float* b_hh   = (const float*)d_in[4];
    const float* W_head = (const float*)d_in[5];
    const float* b_head = (const float*)d_in[6];
    float* out = (float*)d_out;

    tinyrnn_kernel<<<128, 128>>>(x, W_ih, W_hh, b_ih, b_hh, W_head, b_head, out);
}

// round 13
// speedup vs baseline: 1.6415x; 1.0196x over previous
#include <cuda_runtime.h>
#include <cstdint>

// TinyRNN: B=4096, T=2048, I=1, H=12, O=2
// 4 lanes/batch; lane k owns rows {3k..3k+2}; 8 batches/warp;
// 128-thread CTAs (32 batches), grid=128 -> 512 warps (1/SMSP on 128 SMs).
// Exchange via same-warp shared memory, NO syncwarp (validated R11/R12),
// LANE-MAJOR layout: slot float m' = 4*i + k (quad i = h_i of lanes 0..3).
// NEW: six ld.shared.b64 -> each load IS one f32x2 operand (no pack movs);
// STS h_i immediately followed by quad-i's two b64 loads; fma2 chains consume
// pairs in arrival order so post-last-land = fma2 + add2 + fadd + tanh.

#define T_TOTAL 2048
#define NCHUNK  32
#define CH      64
#define XSTRIDE 68   // 64 + 4 pad
#define EXSTRIDE 20  // floats per group slot (80B: 16B-aligned, conflict-free)

__device__ __forceinline__ uint64_t pack2(float lo, float hi) {
    uint64_t r; asm("mov.b64 %0, {%1, %2};" : "=l"(r) : "f"(lo), "f"(hi)); return r;
}
__device__ __forceinline__ void unpack2(uint64_t v, float &lo, float &hi) {
    asm("mov.b64 {%0, %1}, %2;" : "=f"(lo), "=f"(hi) : "l"(v));
}
__device__ __forceinline__ uint64_t mul2(uint64_t a, uint64_t b) {
    uint64_t r; asm("mul.rn.f32x2 %0, %1, %2;" : "=l"(r) : "l"(a), "l"(b)); return r;
}
__device__ __forceinline__ uint64_t fma2(uint64_t a, uint64_t b, uint64_t c) {
    uint64_t r; asm("fma.rn.f32x2 %0, %1, %2, %3;" : "=l"(r) : "l"(a), "l"(b), "l"(c)); return r;
}
__device__ __forceinline__ uint64_t add2(uint64_t a, uint64_t b) {
    uint64_t r; asm("add.rn.f32x2 %0, %1, %2;" : "=l"(r) : "l"(a), "l"(b)); return r;
}
__device__ __forceinline__ float tanhf_hw(float x) {
    float r; asm("tanh.approx.f32 %0, %1;" : "=f"(r) : "f"(x)); return r;
}

__global__ void __launch_bounds__(128, 1) tinyrnn_kernel(
    const float* __restrict__ x,       // [4096, 2048, 1]
    const float* __restrict__ W_ih,    // [12, 1]
    const float* __restrict__ W_hh,    // [12, 12]
    const float* __restrict__ b_ih,    // [12]
    const float* __restrict__ b_hh,    // [12]
    const float* __restrict__ W_head,  // [2, 12]
    const float* __restrict__ b_head,  // [2]
    float* __restrict__ out)           // [4096, 2]
{
    __shared__ float sx[2][32 * XSTRIDE];
    __shared__ __align__(16) float sex[32 * EXSTRIDE];

    const int tid  = threadIdx.x;
    const int lane = tid & 31;
    const int warp = tid >> 5;
    const int k    = lane & 3;              // lane within 4-lane group
    const int wb   = lane >> 2;             // group within warp (0..7)
    const int bic  = warp * 8 + wb;         // batch in CTA (0..31)
    const int batch = blockIdx.x * 32 + bic;

    // weights per owned row r=3k+i, for lane-major pairs:
    // quad q pair a = cols (q, 3+q)  [lanes 0,1];  pair b = cols (6+q, 9+q)
    uint64_t WA[3][3], WB[3][3];
    float A[3], Bx[3];
#pragma unroll
    for (int i = 0; i < 3; i++) {
        const int r = 3 * k + i;
#pragma unroll
        for (int q = 0; q < 3; q++) {
            WA[i][q] = pack2(W_hh[r * 12 + q],     W_hh[r * 12 + 3 + q]);
            WB[i][q] = pack2(W_hh[r * 12 + 6 + q], W_hh[r * 12 + 9 + q]);
        }
        A[i]  = b_ih[r] + b_hh[r];
        Bx[i] = W_ih[r];
    }

    // exchange slot addresses: float m' = 4*i + k  (lane-major)
    const unsigned exb = (unsigned)__cvta_generic_to_shared(&sex[bic * EXSTRIDE]);
    const unsigned st0 = exb + 4u * (unsigned)k;        // h0 -> quad 0
    const unsigned st1 = st0 + 16u;                     // h1 -> quad 1
    const unsigned st2 = st0 + 32u;                     // h2 -> quad 2

    const float* xcta = x + (size_t)blockIdx.x * 32 * T_TOTAL;

    // --- cp.async chunk prefetch: 32 batches x 64 steps = 512 float4 ---
    auto prefetch = [&](int c, int buf) {
#pragma unroll
        for (int rr = 0; rr < 4; rr++) {
            int flat = rr * 128 + tid;      // 0..511
            int b    = flat >> 4;
            int q    = flat & 15;
            const float* src = xcta + (size_t)b * T_TOTAL + c * CH + q * 4;
            unsigned dst = (unsigned)__cvta_generic_to_shared(
                &sx[buf][b * XSTRIDE + q * 4]);
            asm volatile("cp.async.ca.shared.global [%0], [%1], 16;\n"
                         :: "r"(dst), "l"(src));
        }
        asm volatile("cp.async.commit_group;\n");
    };

    prefetch(0, 0);

    float h0 = 0.0f, h1 = 0.0f, h2 = 0.0f;  // own rows 3k..3k+2

    for (int c = 0; c < NCHUNK; c++) {
        const int cur = c & 1;
        if (c + 1 < NCHUNK) {
            prefetch(c + 1, cur ^ 1);
            asm volatile("cp.async.wait_group 1;\n");
        } else {
            asm volatile("cp.async.wait_group 0;\n");
        }
        __syncthreads();

        const float* xs = &sx[cur][bic * XSTRIDE];

#pragma unroll 4
        for (int tt = 0; tt < CH; tt++) {
            const float xt = xs[tt];
            // bias/x init terms, off the serial chain
            const uint64_t U0 = pack2(fmaf(xt, Bx[0], A[0]), 0.0f);
            const uint64_t U1 = pack2(fmaf(xt, Bx[1], A[1]), 0.0f);
            const uint64_t U2 = pack2(fmaf(xt, Bx[2], A[2]), 0.0f);

            // STS h_i immediately followed by quad-i's two b64 loads.
            // Same-warp MIO program order makes each LDS see prior STS.
            // Each b64 load IS one f32x2 operand (no pack movs).
            uint64_t P0a, P0b, P1a, P1b, P2a, P2b;
            asm volatile("st.shared.f32 [%0], %1;" :: "r"(st0), "f"(h0));
            asm volatile("ld.shared.b64 %0, [%1];" : "=l"(P0a) : "r"(exb));
            asm volatile("ld.shared.b64 %0, [%1];" : "=l"(P0b) : "r"(exb + 8u));
            asm volatile("st.shared.f32 [%0], %1;" :: "r"(st1), "f"(h1));
            asm volatile("ld.shared.b64 %0, [%1];" : "=l"(P1a) : "r"(exb + 16u));
            asm volatile("ld.shared.b64 %0, [%1];" : "=l"(P1b) : "r"(exb + 24u));
            asm volatile("st.shared.f32 [%0], %1;" :: "r"(st2), "f"(h2));
            asm volatile("ld.shared.b64 %0, [%1];" : "=l"(P2a) : "r"(exb + 32u));
            asm volatile("ld.shared.b64 %0, [%1];" : "=l"(P2b) : "r"(exb + 40u));

            float hn[3];
            const uint64_t UU[3] = {U0, U1, U2};
#pragma unroll
            for (int i = 0; i < 3; i++) {
                // arrival-ordered: 0a,0b,1a,1b,2a,2b; two parallel chains
                uint64_t aA = fma2(WA[i][0], P0a, UU[i]);
                uint64_t aB = mul2(WB[i][0], P0b);
                aA = fma2(WA[i][1], P1a, aA);
                aB = fma2(WB[i][1], P1b, aB);
                aA = fma2(WA[i][2], P2a, aA);
                aB = fma2(WB[i][2], P2b, aB);
                float lo, hi;
                unpack2(add2(aA, aB), lo, hi);
                hn[i] = tanhf_hw(lo + hi);
            }
            h0 = hn[0]; h1 = hn[1]; h2 = hn[2];
        }
        __syncthreads();
    }

    // --- head: rebuild full h via shfl (one-time; negligible) ---
    float g[12];
    g[3 * k + 0] = h0; g[3 * k + 1] = h1; g[3 * k + 2] = h2;
#pragma unroll
    for (int d = 1; d < 4; d++) {
        const int p = k ^ d;
        g[3 * p + 0] = __shfl_xor_sync(0xffffffffu, h0, d, 4);
        g[3 * p + 1] = __shfl_xor_sync(0xffffffffu, h1, d, 4);
        g[3 * p + 2] = __shfl_xor_sync(0xffffffffu, h2, d, 4);
    }

    if (k == 0) {
        float o0 = b_head[0];
        float o1 = b_head[1];
#pragma unroll
        for (int m = 0; m < 12; m++) {
            o0 = fmaf(W_head[m],      g[m], o0);
            o1 = fmaf(W_head[12 + m], g[m], o1);
        }
        out[batch * 2 + 0] = o0;
        out[batch * 2 + 1] = o1;
    }
}

extern "C" void kernel_launch(void* const* d_in, const int* in_sizes, int n_in,
                              void* d_out, int out_size)
{
    const float* x      = (const float*)d_in[0];
    const float* W_ih   = (const float*)d_in[1];
    const float* W_hh   = (const float*)d_in[2];
    const float* b_ih   = (const float*)d_in[3];
    const float* b_hh   = (const float*)d_in[4];
    const float* W_head = (const float*)d_in[5];
    const float* b_head = (const float*)d_in[6];
    float* out = (float*)d_out;

    tinyrnn_kernel<<<128, 128>>>(x, W_ih, W_hh, b_ih, b_hh, W_head, b_head, out);
}